// round 1
// baseline (speedup 1.0000x reference)
#include <cuda_runtime.h>

// KAN layer: out[b,j] = sum_i silu(x[b,i])*W[i,0,j] + sum_{i,k} exp(-0.5*z_ik^2)*W[i,k+1,j] + bias[j]
// Fused weights W2[i][f][j] (f=0: silu path, f=1..8: RBF basis) precomputed per call.

#define IN_F   128
#define OUT_F  32
#define NB     9            // features per input channel: silu + 8 basis
#define W2_ELEMS (IN_F * NB * OUT_F)   // 36864 floats = 147456 bytes

// Spline constants (grid: linspace(-1,1,12), centers = grid[3:11], spacing = 0.4 + 1e-6)
#define C0_CONST   (-0.45454545454545453f)           // grid[3] = -1 + 6/11
#define SPACING    (0.400001f)
#define HSTEP      (0.18181818181818182f)            // 2/11 center spacing
#define INV_S      (1.0f / SPACING)
#define DELTA      (HSTEP / SPACING)

__device__ float g_w2[W2_ELEMS];   // [i][f][j]
__device__ float g_bias[OUT_F];

// ---------------- f32x2 packed-FMA helpers (ptxas will NOT auto-fuse; must be PTX) --------
__device__ __forceinline__ unsigned long long pack2(float lo, float hi) {
    unsigned long long r;
    asm("mov.b64 %0, {%1, %2};" : "=l"(r) : "f"(lo), "f"(hi));
    return r;
}
__device__ __forceinline__ void unpack2(unsigned long long v, float &lo, float &hi) {
    asm("mov.b64 {%0, %1}, %2;" : "=f"(lo), "=f"(hi) : "l"(v));
}
__device__ __forceinline__ void fma2(unsigned long long &d, unsigned long long a, unsigned long long b) {
    // d = a * b + d   (two independent fp32 FMAs per instruction)
    asm("fma.rn.f32x2 %0, %1, %2, %0;" : "+l"(d) : "l"(a), "l"(b));
}

// ---------------- preprocessing: fuse edge_weights into coeff/base_weight ----------------
__global__ void kan_prep(const float* __restrict__ coeff,
                         const float* __restrict__ base_weight,
                         const float* __restrict__ edge_weights) {
    int i = blockIdx.x;           // 0..127
    int t = threadIdx.x;          // 0..287
    if (t < NB * OUT_F) {
        int f = t >> 5;           // 0..8
        int j = t & 31;           // 0..31
        float e = edge_weights[i * OUT_F + j];
        float v = (f == 0) ? base_weight[i * OUT_F + j]
                           : coeff[i * OUT_F * 8 + j * 8 + (f - 1)];
        g_w2[(i * NB + f) * OUT_F + j] = e * v;
    }
}

__global__ void kan_bias(const float* __restrict__ edge_weights,
                         const float* __restrict__ base_bias) {
    int j = threadIdx.x;          // 0..31
    float s = 0.0f;
    #pragma unroll 4
    for (int i = 0; i < IN_F; i++)
        s += edge_weights[i * OUT_F + j] * base_bias[i * OUT_F + j];
    g_bias[j] = s;
}

// ---------------- main kernel: one row per thread, 16 f32x2 accumulators -----------------
__device__ __forceinline__ void do_input(float xv, const float* __restrict__ wbase,
                                         unsigned long long* acc, const float* q) {
    float f[NB];
    // silu
    float sig = __fdividef(1.0f, 1.0f + __expf(-xv));
    f[0] = xv * sig;
    // Gaussian ladder: basis_k = exp(-0.5*(w - k*DELTA)^2), w = (x - c0)/s
    // basis_0 = exp(-0.5 w^2);  basis_{k+1} = basis_k * t * q_k,  t = exp(DELTA*w),
    // q_k = exp(-DELTA^2*(k+0.5))  -> only 2 exps here instead of 8.
    float w = (xv - C0_CONST) * INV_S;
    float t = __expf(DELTA * w);
    float b = __expf(-0.5f * w * w);
    f[1] = b;
    #pragma unroll
    for (int k = 0; k < 7; k++) { b *= t * q[k]; f[2 + k] = b; }

    #pragma unroll
    for (int ff = 0; ff < NB; ff++) {
        unsigned long long fp = pack2(f[ff], f[ff]);
        const ulonglong2* wp = (const ulonglong2*)(wbase + ff * OUT_F);  // 128B aligned
        #pragma unroll
        for (int p = 0; p < 8; p++) {
            ulonglong2 wv = wp[p];            // broadcast LDS.128 (uniform address)
            fma2(acc[2 * p],     fp, wv.x);
            fma2(acc[2 * p + 1], fp, wv.y);
        }
    }
}

__global__ void __launch_bounds__(256) kan_main(const float* __restrict__ x,
                                                float* __restrict__ out,
                                                int n_rows) {
    extern __shared__ __align__(16) float ws[];   // W2 copy, 147456 bytes

    // cooperative load of W2 into SMEM (float4, coalesced)
    {
        const float4* src = (const float4*)g_w2;
        float4* dst = (float4*)ws;
        #pragma unroll
        for (int v = threadIdx.x; v < W2_ELEMS / 4; v += 256) dst[v] = src[v];
    }
    __syncthreads();

    int row = blockIdx.x * 256 + threadIdx.x;
    if (row >= n_rows) return;

    // per-thread ladder constants (7 cheap MUFU, folded across whole row)
    float q[7];
    const float D2 = DELTA * DELTA;
    #pragma unroll
    for (int k = 0; k < 7; k++) q[k] = __expf(-D2 * ((float)k + 0.5f));

    unsigned long long acc[16];
    #pragma unroll
    for (int p = 0; p < 16; p++) acc[p] = pack2(g_bias[2 * p], g_bias[2 * p + 1]);

    const float4* xr = (const float4*)(x + (size_t)row * IN_F);

    #pragma unroll 1
    for (int i4 = 0; i4 < IN_F / 4; i4++) {
        float4 xv = xr[i4];
        const float* wb = ws + (i4 * 4) * (NB * OUT_F);
        do_input(xv.x, wb + 0 * (NB * OUT_F), acc, q);
        do_input(xv.y, wb + 1 * (NB * OUT_F), acc, q);
        do_input(xv.z, wb + 2 * (NB * OUT_F), acc, q);
        do_input(xv.w, wb + 3 * (NB * OUT_F), acc, q);
    }

    float4* orow = (float4*)(out + (size_t)row * OUT_F);
    #pragma unroll
    for (int p = 0; p < 8; p++) {
        float4 v;
        unpack2(acc[2 * p],     v.x, v.y);
        unpack2(acc[2 * p + 1], v.z, v.w);
        orow[p] = v;
    }
}

// ---------------- launch ----------------
extern "C" void kernel_launch(void* const* d_in, const int* in_sizes, int n_in,
                              void* d_out, int out_size) {
    const float* x      = (const float*)d_in[0];
    const float* coeff  = (const float*)d_in[1];
    const float* bw     = (const float*)d_in[2];
    const float* bb     = (const float*)d_in[3];
    const float* ew     = (const float*)d_in[4];
    float* out          = (float*)d_out;

    int n_rows = in_sizes[0] / IN_F;   // 131072

    cudaFuncSetAttribute(kan_main, cudaFuncAttributeMaxDynamicSharedMemorySize,
                         W2_ELEMS * (int)sizeof(float));

    kan_prep<<<IN_F, NB * OUT_F>>>(coeff, bw, ew);
    kan_bias<<<1, OUT_F>>>(ew, bb);

    int grid = (n_rows + 255) / 256;   // 512
    kan_main<<<grid, 256, W2_ELEMS * sizeof(float)>>>(x, out, n_rows);
}

// round 7
// speedup vs baseline: 2.5157x; 2.5157x over previous
#include <cuda_runtime.h>
#include <cuda_bf16.h>
#include <cstdint>

// KAN layer as split-bf16 warp-MMA GEMM (no tcgen05: ptxas target is sm_103
// without the 'a' feature set; mma.sync/ldmatrix are arch-neutral).
//   out[131072,32] = F[131072,1280] x W[1280,32] + bias
//   F: per 16-ch chunk, k-slot = (f>>1)*32 + ch*2 + (f&1), 10 pairs (last pad 0)
//   3 slabs: Fhi*Whi + Flo*Whi + Fhi*Wlo  (fp32 accum in HMMA)

#define IN_F   128
#define OUT_F  32
#define TILE_M 128
#define THREADS 256
#define NCHUNKS 8
#define KSC    10                       // k16-steps per chunk
#define NKS    (NCHUNKS * KSC)          // 80
#define APITCH   168                    // bf16 per A row (bank-friendly, 16B rows)
#define APITCH_B 336
#define ABUF   (TILE_M * APITCH_B)      // 43008 bytes per precision
#define SMEM_TOTAL (2 * ABUF)           // 86016 -> 2 CTAs/SM

#define C0_CONST (-0.45454545454545453f)
#define SPACING  (0.400001f)
#define INV_S    (1.0f / SPACING)
#define DELTA    (0.18181818181818182f / SPACING)

// W in B-fragment-packed order: [(ks*4+nt)*32 + lane] -> {reg0,reg1} as u64
__device__ unsigned long long g_whf[NKS * 4 * 32];
__device__ unsigned long long g_wlf[NKS * 4 * 32];
__device__ float g_bias[OUT_F];

// ---------------- helpers ----------------
static __device__ __forceinline__ uint32_t smem_u32(const void* p) {
    uint32_t a;
    asm("{ .reg .u64 t; cvta.to.shared.u64 t, %1; cvt.u32.u64 %0, t; }" : "=r"(a) : "l"(p));
    return a;
}
static __device__ __forceinline__ uint32_t bf2(float hi, float lo) {
    uint32_t r;
    asm("cvt.rn.bf16x2.f32 %0, %1, %2;" : "=r"(r) : "f"(hi), "f"(lo));
    return r;
}
static __device__ __forceinline__ void ldm4(uint32_t* r, uint32_t addr) {
    asm volatile("ldmatrix.sync.aligned.m8n8.x4.shared.b16 {%0,%1,%2,%3}, [%4];"
                 : "=r"(r[0]), "=r"(r[1]), "=r"(r[2]), "=r"(r[3]) : "r"(addr));
}
static __device__ __forceinline__ void mma16816(float* d, const uint32_t* a,
                                                uint32_t b0, uint32_t b1) {
    asm volatile(
        "mma.sync.aligned.m16n8k16.row.col.f32.bf16.bf16.f32 "
        "{%0,%1,%2,%3}, {%4,%5,%6,%7}, {%8,%9}, {%0,%1,%2,%3};"
        : "+f"(d[0]), "+f"(d[1]), "+f"(d[2]), "+f"(d[3])
        : "r"(a[0]), "r"(a[1]), "r"(a[2]), "r"(a[3]), "r"(b0), "r"(b1));
}

// ---------------- prep: fuse edge weights, split hi/lo, B-fragment pack ----------------
__global__ void kan_prep(const float* __restrict__ coeff, const float* __restrict__ bw,
                         const float* __restrict__ ew) {
    int i = blockIdx.x;                 // channel 0..127
    int t = threadIdx.x;                // 320 = 10 f-slots x 32 j
    int f = t >> 5, j = t & 31;         // f 0..9 (9 = pad slot, value 0)
    float v = 0.0f;
    if (f < 9) {
        float e = ew[i * OUT_F + j];
        v = e * ((f == 0) ? bw[i * OUT_F + j] : coeff[(i * OUT_F + j) * 8 + (f - 1)]);
    }
    __nv_bfloat16 h = __float2bfloat16(v);
    __nv_bfloat16 l = __float2bfloat16(v - __bfloat162float(h));

    int kg = (i >> 4) * 160 + (f >> 1) * 32 + (i & 15) * 2 + (f & 1);
    int ks = kg >> 4, kr = kg & 15;
    int lane = (j & 7) * 4 + ((kr >> 1) & 3);
    int idx = (((ks * 4 + (j >> 3)) * 32 + lane) * 2 + (kr >> 3)) * 2 + (kr & 1);
    ((__nv_bfloat16*)g_whf)[idx] = h;
    ((__nv_bfloat16*)g_wlf)[idx] = l;
}

__global__ void kan_bias(const float* __restrict__ ew, const float* __restrict__ bb) {
    int j = threadIdx.x;
    float s = 0.0f;
    #pragma unroll 4
    for (int i = 0; i < IN_F; i++) s += ew[i * OUT_F + j] * bb[i * OUT_F + j];
    g_bias[j] = s;
}

// ---------------- main ----------------
__global__ void __launch_bounds__(THREADS, 2) kan_main(const float* __restrict__ x,
                                                       float* __restrict__ out) {
    extern __shared__ __align__(16) char sm[];
    const uint32_t smb = smem_u32(sm);
    const int tid = threadIdx.x;
    const int w = tid >> 5;             // warp 0..7, rows w*16..w*16+15
    const int L = tid & 31;
    const int ch = tid & 15;            // producer channel-in-chunk
    const int rg = tid >> 4;            // producer row group 0..15 (rows rg+16p)
    const size_t tile = (size_t)blockIdx.x * TILE_M;

    // gaussian ladder constants
    float q[7];
    const float D2 = DELTA * DELTA;
    #pragma unroll
    for (int k = 0; k < 7; k++) q[k] = __expf(-D2 * ((float)k + 0.5f));

    float acc[16];
    #pragma unroll
    for (int i = 0; i < 16; i++) acc[i] = 0.0f;

    const float* xp = x + (tile + rg) * IN_F + ch;

    // producer store base (hi slab); lo slab at +ABUF
    char* stb = sm + rg * APITCH_B + ch * 4;

    // ldmatrix address: lane -> (row, k-half) of the four 8x8 tiles
    const int qq = L >> 3, rr = L & 7;
    const uint32_t lm_hi = smb + (uint32_t)((w * 16 + rr + (qq & 1) * 8) * APITCH_B
                                            + (qq >> 1) * 16);

    // x prefetch (chunk 0)
    float xv[8];
    #pragma unroll
    for (int p = 0; p < 8; p++) xv[p] = xp[p * 16 * IN_F];

    for (int c = 0; c < NCHUNKS; c++) {
        float xn[8];
        if (c < NCHUNKS - 1) {
            #pragma unroll
            for (int p = 0; p < 8; p++) xn[p] = xp[p * 16 * IN_F + (c + 1) * 16];
        }

        // ---- produce features for this chunk ----
        #pragma unroll
        for (int p = 0; p < 8; p++) {
            float X = xv[p];
            float fa[9];
            fa[0] = X * __fdividef(1.0f, 1.0f + __expf(-X));     // silu
            float wz = (X - C0_CONST) * INV_S;
            float tt = __expf(DELTA * wz);
            float b = __expf(-0.5f * wz * wz);
            fa[1] = b;
            #pragma unroll
            for (int k = 0; k < 7; k++) { b *= tt * q[k]; fa[2 + k] = b; }

            uint32_t uh[5];
            uh[0] = bf2(fa[1], fa[0]); uh[1] = bf2(fa[3], fa[2]);
            uh[2] = bf2(fa[5], fa[4]); uh[3] = bf2(fa[7], fa[6]);
            uh[4] = bf2(0.0f, fa[8]);
            float l0 = fa[0] - __uint_as_float(uh[0] << 16);
            float l1 = fa[1] - __uint_as_float(uh[0] & 0xFFFF0000u);
            float l2 = fa[2] - __uint_as_float(uh[1] << 16);
            float l3 = fa[3] - __uint_as_float(uh[1] & 0xFFFF0000u);
            float l4 = fa[4] - __uint_as_float(uh[2] << 16);
            float l5 = fa[5] - __uint_as_float(uh[2] & 0xFFFF0000u);
            float l6 = fa[6] - __uint_as_float(uh[3] << 16);
            float l7 = fa[7] - __uint_as_float(uh[3] & 0xFFFF0000u);
            float l8 = fa[8] - __uint_as_float(uh[4] << 16);
            uint32_t ul[5];
            ul[0] = bf2(l1, l0); ul[1] = bf2(l3, l2);
            ul[2] = bf2(l5, l4); ul[3] = bf2(l7, l6);
            ul[4] = bf2(0.0f, l8);

            char* a = stb + p * (16 * APITCH_B);
            #pragma unroll
            for (int j = 0; j < 5; j++) {
                *(uint32_t*)(a + j * 64)        = uh[j];
                *(uint32_t*)(a + j * 64 + ABUF) = ul[j];
            }
        }
        #pragma unroll
        for (int p = 0; p < 8; p++) xv[p] = xn[p];

        __syncthreads();

        // ---- MMA over 10 k16-steps ----
        const unsigned long long* __restrict__ wh = g_whf + (size_t)(c * KSC) * 4 * 32 + L;
        const unsigned long long* __restrict__ wl = g_wlf + (size_t)(c * KSC) * 4 * 32 + L;
        #pragma unroll
        for (int ks = 0; ks < KSC; ks++) {
            // B fragments first: give LDG->HMMA scoreboard maximum slack
            unsigned long long bh[4], bl[4];
            #pragma unroll
            for (int nt = 0; nt < 4; nt++) {
                bh[nt] = wh[(ks * 4 + nt) * 32];
                bl[nt] = wl[(ks * 4 + nt) * 32];
            }
            uint32_t ah[4], al[4];
            ldm4(ah, lm_hi + ks * 32);
            ldm4(al, lm_hi + ks * 32 + ABUF);
            #pragma unroll
            for (int nt = 0; nt < 4; nt++) {
                uint32_t bh0 = (uint32_t)bh[nt], bh1 = (uint32_t)(bh[nt] >> 32);
                uint32_t bl0 = (uint32_t)bl[nt], bl1 = (uint32_t)(bl[nt] >> 32);
                mma16816(acc + nt * 4, ah, bh0, bh1);   // Fhi * Whi
                mma16816(acc + nt * 4, al, bh0, bh1);   // Flo * Whi
                mma16816(acc + nt * 4, ah, bl0, bl1);   // Fhi * Wlo
            }
        }
        __syncthreads();
    }

    // ---- epilogue: fragment -> global, + bias ----
    size_t r0 = tile + w * 16 + (L >> 2);
    int cb = (L & 3) * 2;
    #pragma unroll
    for (int nt = 0; nt < 4; nt++) {
        int col = nt * 8 + cb;
        float b0 = g_bias[col], b1 = g_bias[col + 1];
        float2 v0 = make_float2(acc[nt * 4 + 0] + b0, acc[nt * 4 + 1] + b1);
        float2 v1 = make_float2(acc[nt * 4 + 2] + b0, acc[nt * 4 + 3] + b1);
        *(float2*)(out + r0 * OUT_F + col)       = v0;
        *(float2*)(out + (r0 + 8) * OUT_F + col) = v1;
    }
}

// ---------------- launch ----------------
extern "C" void kernel_launch(void* const* d_in, const int* in_sizes, int n_in,
                              void* d_out, int out_size) {
    const float* x     = (const float*)d_in[0];
    const float* coeff = (const float*)d_in[1];
    const float* bw    = (const float*)d_in[2];
    const float* bb    = (const float*)d_in[3];
    const float* ew    = (const float*)d_in[4];
    float* out         = (float*)d_out;

    int n_rows = in_sizes[0] / IN_F;           // 131072
    int grid   = n_rows / TILE_M;              // 1024

    cudaFuncSetAttribute(kan_main, cudaFuncAttributeMaxDynamicSharedMemorySize, SMEM_TOTAL);

    kan_prep<<<IN_F, 320>>>(coeff, bw, ew);
    kan_bias<<<1, OUT_F>>>(ew, bb);
    kan_main<<<grid, THREADS, SMEM_TOTAL>>>(x, out);
}

// round 9
// speedup vs baseline: 2.6826x; 1.0663x over previous
#include <cuda_runtime.h>
#include <cuda_bf16.h>
#include <cstdint>

// KAN layer as single-slab tf32 warp-MMA GEMM (tcgen05 is ptxas-gated off:
// target is plain sm_103; mma.sync/ldmatrix-free tf32 path is arch-neutral).
//   out[131072,32] = F[131072,1152] x W[1152,32] + bias
//   F: per 16-ch chunk, k-slot = f*16 + ch (9 features x 16 channels = 144/chunk)
//   tf32 inputs (cvt.rna), fp32 accumulate. Predicted rel_err ~2e-4.

#define IN_F    128
#define OUT_F   32
#define TILE_M  128
#define THREADS 256
#define NCHUNKS 8
#define KSC     18                      // k8-steps per chunk (144/8)
#define NKS     (NCHUNKS * KSC)         // 144 total k8-steps
#define WBLK    (KSC * 512)             // 9216 B per warp A-block per chunk... per warp
#define ABUF    (8 * WBLK)              // 73728 B = 128 rows x 144 k x 4B
#define SMEM_TOTAL ABUF

#define C0_CONST (-0.45454545454545453f)
#define SPACING  (0.400001f)
#define INV_S    (1.0f / SPACING)
#define DELTA    (0.18181818181818182f / SPACING)

// W in B-fragment order: uint4[(ks*2 + nthalf)*32 + lane] = {b0,b1 of nt=2h, b0,b1 of nt=2h+1}
__device__ uint4 g_wf[NKS * 2 * 32];
__device__ float g_bias[OUT_F];

// ---------------- helpers ----------------
static __device__ __forceinline__ uint32_t smem_u32(const void* p) {
    uint32_t a;
    asm("{ .reg .u64 t; cvta.to.shared.u64 t, %1; cvt.u32.u64 %0, t; }" : "=r"(a) : "l"(p));
    return a;
}
static __device__ __forceinline__ uint32_t tf32(float v) {
    uint32_t r;
    asm("cvt.rna.tf32.f32 %0, %1;" : "=r"(r) : "f"(v));
    return r;
}
static __device__ __forceinline__ void mma1688(float* d, const uint32_t* a,
                                               uint32_t b0, uint32_t b1) {
    asm volatile(
        "mma.sync.aligned.m16n8k8.row.col.f32.tf32.tf32.f32 "
        "{%0,%1,%2,%3}, {%4,%5,%6,%7}, {%8,%9}, {%0,%1,%2,%3};"
        : "+f"(d[0]), "+f"(d[1]), "+f"(d[2]), "+f"(d[3])
        : "r"(a[0]), "r"(a[1]), "r"(a[2]), "r"(a[3]), "r"(b0), "r"(b1));
}

// ---------------- prep: fuse edge weights, tf32-convert, B-fragment pack ----------------
__global__ void kan_prep(const float* __restrict__ coeff, const float* __restrict__ bw,
                         const float* __restrict__ ew) {
    int i = blockIdx.x;                 // channel 0..127
    int t = threadIdx.x;                // 288 = 9 f x 32 j
    int f = t >> 5, j = t & 31;
    float e = ew[i * OUT_F + j];
    float v = e * ((f == 0) ? bw[i * OUT_F + j] : coeff[(i * OUT_F + j) * 8 + (f - 1)]);

    int k   = (i >> 4) * 144 + f * 16 + (i & 15);
    int ks  = k >> 3, k8 = k & 7;
    int tig = k8 & 3, bsel = k8 >> 2;           // b0 (k%8<4) or b1
    int lane = (j & 7) * 4 + tig;
    int nt  = j >> 3, h = nt >> 1;
    int slot = (nt & 1) * 2 + bsel;
    int idx = ((ks * 2 + h) * 32 + lane) * 4 + slot;
    ((uint32_t*)g_wf)[idx] = tf32(v);
}

__global__ void kan_bias(const float* __restrict__ ew, const float* __restrict__ bb) {
    int j = threadIdx.x;
    float s = 0.0f;
    #pragma unroll 4
    for (int i = 0; i < IN_F; i++) s += ew[i * OUT_F + j] * bb[i * OUT_F + j];
    g_bias[j] = s;
}

// ---------------- main ----------------
__global__ void __launch_bounds__(THREADS, 2) kan_main(const float* __restrict__ x,
                                                       float* __restrict__ out) {
    extern __shared__ __align__(16) char sm[];
    const uint32_t smb = smem_u32(sm);
    const int tid = threadIdx.x;
    const int w = tid >> 5;             // MMA warp: rows w*16..w*16+15
    const int L = tid & 31;
    const int ch = tid & 15;            // producer channel-in-chunk
    const int rg = tid >> 4;            // producer row-in-warpblock (0..15)
    const size_t tile = (size_t)blockIdx.x * TILE_M;

    // gaussian ladder constants
    float q[7];
    const float D2 = DELTA * DELTA;
    #pragma unroll
    for (int k = 0; k < 7; k++) q[k] = __expf(-D2 * ((float)k + 0.5f));

    float acc[16];
    #pragma unroll
    for (int i = 0; i < 16; i++) acc[i] = 0.0f;

    const float* xp = x + (tile + rg) * IN_F + ch;

    // producer store base: element (row = rg + 16p, k = f*16 + ch)
    //   ks = 2f + (ch>>3); lane = (rg&7)*4 + (ch&3); reg = (rg>>3) + 2*((ch>>2)&1)
    //   addr = p*WBLK + ks*512 + lane*16 + reg*4
    const uint32_t pbase = (uint32_t)((ch >> 3) * 512
                                      + ((rg & 7) * 4 + (ch & 3)) * 16
                                      + ((rg >> 3) + 2 * ((ch >> 2) & 1)) * 4);

    // consumer A-fragment address: one LDS.128 per ks
    const uint32_t lmb = smb + (uint32_t)(w * WBLK + L * 16);

    // x prefetch (chunk 0)
    float xv[8];
    #pragma unroll
    for (int p = 0; p < 8; p++) xv[p] = xp[p * 16 * IN_F];

    for (int c = 0; c < NCHUNKS; c++) {
        float xn[8];
        if (c < NCHUNKS - 1) {
            #pragma unroll
            for (int p = 0; p < 8; p++) xn[p] = xp[p * 16 * IN_F + (c + 1) * 16];
        }

        // ---- produce 9 tf32 features per element, store in A-fragment order ----
        #pragma unroll
        for (int p = 0; p < 8; p++) {
            float X = xv[p];
            float fa[9];
            fa[0] = X * __fdividef(1.0f, 1.0f + __expf(-X));     // silu
            float wz = (X - C0_CONST) * INV_S;
            float tt = __expf(DELTA * wz);
            float b = __expf(-0.5f * wz * wz);
            fa[1] = b;
            #pragma unroll
            for (int k = 0; k < 7; k++) { b *= tt * q[k]; fa[2 + k] = b; }

            char* a = sm + pbase + p * WBLK;
            #pragma unroll
            for (int f = 0; f < 9; f++)
                *(uint32_t*)(a + f * 1024) = tf32(fa[f]);        // ks stride 2*512
        }
        #pragma unroll
        for (int p = 0; p < 8; p++) xv[p] = xn[p];

        __syncthreads();

        // ---- MMA over 18 k8-steps ----
        const uint4* __restrict__ wq = g_wf + (size_t)(c * KSC) * 2 * 32 + L;
        #pragma unroll
        for (int ks = 0; ks < KSC; ks++) {
            uint4 b0 = wq[(ks * 2 + 0) * 32];    // nt 0,1
            uint4 b1 = wq[(ks * 2 + 1) * 32];    // nt 2,3
            uint32_t a[4];
            asm volatile("ld.shared.v4.b32 {%0,%1,%2,%3}, [%4];"
                         : "=r"(a[0]), "=r"(a[1]), "=r"(a[2]), "=r"(a[3])
                         : "r"(lmb + ks * 512));
            mma1688(acc + 0,  a, b0.x, b0.y);
            mma1688(acc + 4,  a, b0.z, b0.w);
            mma1688(acc + 8,  a, b1.x, b1.y);
            mma1688(acc + 12, a, b1.z, b1.w);
        }
        __syncthreads();
    }

    // ---- epilogue: fragment -> global, + bias ----
    size_t r0 = tile + w * 16 + (L >> 2);
    int cb = (L & 3) * 2;
    #pragma unroll
    for (int nt = 0; nt < 4; nt++) {
        int col = nt * 8 + cb;
        float b0 = g_bias[col], b1 = g_bias[col + 1];
        float2 v0 = make_float2(acc[nt * 4 + 0] + b0, acc[nt * 4 + 1] + b1);
        float2 v1 = make_float2(acc[nt * 4 + 2] + b0, acc[nt * 4 + 3] + b1);
        *(float2*)(out + r0 * OUT_F + col)       = v0;
        *(float2*)(out + (r0 + 8) * OUT_F + col) = v1;
    }
}

// ---------------- launch ----------------
extern "C" void kernel_launch(void* const* d_in, const int* in_sizes, int n_in,
                              void* d_out, int out_size) {
    const float* x     = (const float*)d_in[0];
    const float* coeff = (const float*)d_in[1];
    const float* bw    = (const float*)d_in[2];
    const float* bb    = (const float*)d_in[3];
    const float* ew    = (const float*)d_in[4];
    float* out         = (float*)d_out;

    int n_rows = in_sizes[0] / IN_F;           // 131072
    int grid   = n_rows / TILE_M;              // 1024

    cudaFuncSetAttribute(kan_main, cudaFuncAttributeMaxDynamicSharedMemorySize, SMEM_TOTAL);

    kan_prep<<<IN_F, 288>>>(coeff, bw, ew);
    kan_bias<<<1, OUT_F>>>(ew, bb);
    kan_main<<<grid, THREADS, SMEM_TOTAL>>>(x, out);
}

// round 10
// speedup vs baseline: 4.4098x; 1.6439x over previous
#include <cuda_runtime.h>
#include <cuda_fp16.h>
#include <cstdint>

// KAN layer as single-slab fp16 warp-MMA GEMM.
//   out[131072,32] = F[131072,1280] x W[1280,32] + bias
//   K layout: per 16-ch chunk, k = ch*10 + f  (f=0..8 features, f=9 zero pad)
//   fp16 inputs (11-bit significand == tf32), fp32 accumulate in HMMA.
//   m16n8k16 fp16 runs at full HMMA rate (rt~16, 128 MACs/cyc/SMSP) vs
//   tf32 m16n8k8 (~42 MACs/cyc measured R9) -> MMA floor ~41us.

#define IN_F    128
#define OUT_F   32
#define TILE_M  128
#define THREADS 256
#define NCHUNKS 8
#define KSC     10                      // k16-steps per chunk (160/16)
#define NKS     (NCHUNKS * KSC)         // 80
#define WBLK    (KSC * 512)             // 5120 B: per-MMA-warp A block per chunk
#define SMEM_TOTAL (8 * WBLK)           // 40960 B -> 3 CTAs/SM

#define C0_CONST (-0.45454545454545453f)
#define SPACING  (0.400001f)
#define INV_S    (1.0f / SPACING)
#define DELTA    (0.18181818181818182f / SPACING)

// W in B-fragment order: uint4[(ks*2 + h)*32 + lane] = {nt=2h:{b0,b1}, nt=2h+1:{b0,b1}}
// zero-init covers the f=9 pad slots (prep writes only f<=8).
__device__ uint4 g_wf[NKS * 2 * 32];
__device__ float g_bias[OUT_F];

// ---------------- helpers ----------------
static __device__ __forceinline__ uint32_t smem_u32(const void* p) {
    uint32_t a;
    asm("{ .reg .u64 t; cvta.to.shared.u64 t, %1; cvt.u32.u64 %0, t; }" : "=r"(a) : "l"(p));
    return a;
}
static __device__ __forceinline__ uint32_t fh2(float hi, float lo) {
    uint32_t r;                          // first src -> upper half, second -> lower
    asm("cvt.rn.f16x2.f32 %0, %1, %2;" : "=r"(r) : "f"(hi), "f"(lo));
    return r;
}
static __device__ __forceinline__ float tanh_approx(float v) {
    float r;
    asm("tanh.approx.f32 %0, %1;" : "=f"(r) : "f"(v));
    return r;
}
static __device__ __forceinline__ void mma16816h(float* d, const uint32_t* a,
                                                 uint32_t b0, uint32_t b1) {
    asm volatile(
        "mma.sync.aligned.m16n8k16.row.col.f32.f16.f16.f32 "
        "{%0,%1,%2,%3}, {%4,%5,%6,%7}, {%8,%9}, {%0,%1,%2,%3};"
        : "+f"(d[0]), "+f"(d[1]), "+f"(d[2]), "+f"(d[3])
        : "r"(a[0]), "r"(a[1]), "r"(a[2]), "r"(a[3]), "r"(b0), "r"(b1));
}

// ---------------- prep: fuse edge weights, fp16-convert, B-fragment pack ----------------
__global__ void kan_prep(const float* __restrict__ coeff, const float* __restrict__ bw,
                         const float* __restrict__ ew) {
    int i = blockIdx.x;                 // channel 0..127
    int t = threadIdx.x;                // 288 = 9 f x 32 j
    int f = t >> 5, j = t & 31;
    float e = ew[i * OUT_F + j];
    float v = e * ((f == 0) ? bw[i * OUT_F + j] : coeff[(i * OUT_F + j) * 8 + (f - 1)]);

    int k    = (i >> 4) * 160 + (i & 15) * 10 + f;
    int ks   = k >> 4, kr = k & 15;
    int kw   = kr >> 1, half = kr & 1;  // word-in-k16, half (0=low=even k)
    int lane = (j & 7) * 4 + (kw & 3);
    int nt   = j >> 3, h = nt >> 1;
    int slot = (nt & 1) * 2 + (kw >> 2);          // {b0,b1} of each nt
    int idx  = (((ks * 2 + h) * 32 + lane) * 4 + slot) * 2 + half;
    ((__half*)g_wf)[idx] = __float2half_rn(v);
}

__global__ void kan_bias(const float* __restrict__ ew, const float* __restrict__ bb) {
    int j = threadIdx.x;
    float s = 0.0f;
    #pragma unroll 4
    for (int i = 0; i < IN_F; i++) s += ew[i * OUT_F + j] * bb[i * OUT_F + j];
    g_bias[j] = s;
}

// ---------------- main ----------------
__global__ void __launch_bounds__(THREADS, 3) kan_main(const float* __restrict__ x,
                                                       float* __restrict__ out) {
    extern __shared__ __align__(16) char sm[];
    const uint32_t smb = smem_u32(sm);
    const int tid = threadIdx.x;
    const int w = tid >> 5;             // MMA warp: rows w*16..w*16+15
    const int L = tid & 31;
    const int ch = tid & 15;            // producer channel-in-chunk
    const int rg = tid >> 4;            // producer row-in-block (0..15)
    const size_t tile = (size_t)blockIdx.x * TILE_M;

    // gaussian ladder constants
    float q[7];
    const float D2 = DELTA * DELTA;
    #pragma unroll
    for (int k = 0; k < 7; k++) q[k] = __expf(-D2 * ((float)k + 0.5f));

    float acc[16];
    #pragma unroll
    for (int i = 0; i < 16; i++) acc[i] = 0.0f;

    const float* xp = x + (tile + rg) * IN_F + ch;

    // producer store offsets for the 5 f16x2 words (independent of p)
    uint32_t off[5];
    #pragma unroll
    for (int widx = 0; widx < 5; widx++) {
        int kwl = 5 * ch + widx;        // word index within chunk K (0..79)
        int ks = kwl >> 3, kwi = kwl & 7;
        off[widx] = (uint32_t)(ks * 512 + ((rg & 7) * 4 + (kwi & 3)) * 16
                               + ((rg >> 3) + 2 * (kwi >> 2)) * 4);
    }

    // consumer A-fragment base: one LDS.128 per ks
    const uint32_t lmb = smb + (uint32_t)(w * WBLK + L * 16);

    // x prefetch (chunk 0)
    float xv[8];
    #pragma unroll
    for (int p = 0; p < 8; p++) xv[p] = xp[p * 16 * IN_F];

    for (int c = 0; c < NCHUNKS; c++) {
        float xn[8];
        if (c < NCHUNKS - 1) {
            #pragma unroll
            for (int p = 0; p < 8; p++) xn[p] = xp[p * 16 * IN_F + (c + 1) * 16];
        }

        // ---- produce 9 features per element, pack f16x2, store in fragment order ----
        #pragma unroll
        for (int p = 0; p < 8; p++) {
            float X = xv[p];
            float fa[9];
            // silu via 1-MUFU tanh: sigmoid(x) = 0.5*(1 + tanh(x/2))
            fa[0] = X * (0.5f * tanh_approx(0.5f * X) + 0.5f);
            float wz = (X - C0_CONST) * INV_S;
            float tt = __expf(DELTA * wz);
            float b = __expf(-0.5f * wz * wz);
            fa[1] = b;
            #pragma unroll
            for (int k = 0; k < 7; k++) { b *= tt * q[k]; fa[2 + k] = b; }

            char* a = sm + p * WBLK;
            *(uint32_t*)(a + off[0]) = fh2(fa[1], fa[0]);
            *(uint32_t*)(a + off[1]) = fh2(fa[3], fa[2]);
            *(uint32_t*)(a + off[2]) = fh2(fa[5], fa[4]);
            *(uint32_t*)(a + off[3]) = fh2(fa[7], fa[6]);
            *(uint32_t*)(a + off[4]) = fh2(0.0f,  fa[8]);   // f=9 pad = 0
        }
        #pragma unroll
        for (int p = 0; p < 8; p++) xv[p] = xn[p];

        __syncthreads();

        // ---- MMA over 10 k16-steps ----
        const uint4* __restrict__ wq = g_wf + (size_t)(c * KSC) * 2 * 32 + L;
        #pragma unroll
        for (int ks = 0; ks < KSC; ks++) {
            uint4 b0 = wq[(ks * 2 + 0) * 32];    // nt 0,1
            uint4 b1 = wq[(ks * 2 + 1) * 32];    // nt 2,3
            uint32_t a[4];
            asm volatile("ld.shared.v4.b32 {%0,%1,%2,%3}, [%4];"
                         : "=r"(a[0]), "=r"(a[1]), "=r"(a[2]), "=r"(a[3])
                         : "r"(lmb + ks * 512));
            mma16816h(acc + 0,  a, b0.x, b0.y);
            mma16816h(acc + 4,  a, b0.z, b0.w);
            mma16816h(acc + 8,  a, b1.x, b1.y);
            mma16816h(acc + 12, a, b1.z, b1.w);
        }
        __syncthreads();
    }

    // ---- epilogue: fragment -> global, + bias ----
    size_t r0 = tile + w * 16 + (L >> 2);
    int cb = (L & 3) * 2;
    #pragma unroll
    for (int nt = 0; nt < 4; nt++) {
        int col = nt * 8 + cb;
        float b0 = g_bias[col], b1 = g_bias[col + 1];
        float2 v0 = make_float2(acc[nt * 4 + 0] + b0, acc[nt * 4 + 1] + b1);
        float2 v1 = make_float2(acc[nt * 4 + 2] + b0, acc[nt * 4 + 3] + b1);
        *(float2*)(out + r0 * OUT_F + col)       = v0;
        *(float2*)(out + (r0 + 8) * OUT_F + col) = v1;
    }
}

// ---------------- launch ----------------
extern "C" void kernel_launch(void* const* d_in, const int* in_sizes, int n_in,
                              void* d_out, int out_size) {
    const float* x     = (const float*)d_in[0];
    const float* coeff = (const float*)d_in[1];
    const float* bw    = (const float*)d_in[2];
    const float* bb    = (const float*)d_in[3];
    const float* ew    = (const float*)d_in[4];
    float* out         = (float*)d_out;

    int n_rows = in_sizes[0] / IN_F;           // 131072
    int grid   = n_rows / TILE_M;              // 1024

    kan_prep<<<IN_F, 288>>>(coeff, bw, ew);
    kan_bias<<<1, OUT_F>>>(ew, bb);
    kan_main<<<grid, THREADS, SMEM_TOTAL>>>(x, out);
}

// round 15
// speedup vs baseline: 4.9426x; 1.1208x over previous
#include <cuda_runtime.h>
#include <cuda_fp16.h>
#include <cstdint>

// KAN layer as single-slab fp16 warp-MMA GEMM, software-pipelined.
//   out[131072,32] = F[131072,1152] x W[1152,32] + bias   (no K pad)
//   K layout: per 16-ch chunk, k = f*16 + ch  -> adjacent k = channel pair,
//   so f16x2 words pack two channels' same feature. 9 k16-steps per chunk.
//   Double-buffered A; produce(c+1) interleaved into MMA(c); 1 barrier/chunk.

#define IN_F    128
#define OUT_F   32
#define TILE_M  128
#define THREADS 256
#define NCHUNKS 8
#define KSC     9                        // k16-steps per chunk (144/16)
#define NKS     (NCHUNKS * KSC)          // 72
#define WBLK    (KSC * 512)              // 4608 B per 16-row block per chunk
#define ABUF    (8 * WBLK)               // 36864 B per buffer
#define SMEM_TOTAL (2 * ABUF)            // 73728 -> 2 CTAs/SM

#define C0_CONST (-0.45454545454545453f)
#define SPACING  (0.400001f)
#define INV_S    (1.0f / SPACING)
#define DELTA    (0.18181818181818182f / SPACING)

// W in B-fragment order: uint4[(ks*2 + h)*32 + lane] = {nt=2h:{b0,b1}, nt=2h+1:{b0,b1}}
__device__ uint4 g_wf[NKS * 2 * 32];
__device__ float g_bias[OUT_F];

// ---------------- helpers ----------------
static __device__ __forceinline__ uint32_t smem_u32(const void* p) {
    uint32_t a;
    asm("{ .reg .u64 t; cvta.to.shared.u64 t, %1; cvt.u32.u64 %0, t; }" : "=r"(a) : "l"(p));
    return a;
}
static __device__ __forceinline__ uint32_t fh2(float hi, float lo) {
    uint32_t r;
    asm("cvt.rn.f16x2.f32 %0, %1, %2;" : "=r"(r) : "f"(hi), "f"(lo));
    return r;
}
static __device__ __forceinline__ float tanh_approx(float v) {
    float r;
    asm("tanh.approx.f32 %0, %1;" : "=f"(r) : "f"(v));
    return r;
}
static __device__ __forceinline__ void mma16816h(float* d, const uint32_t* a,
                                                 uint32_t b0, uint32_t b1) {
    asm volatile(
        "mma.sync.aligned.m16n8k16.row.col.f32.f16.f16.f32 "
        "{%0,%1,%2,%3}, {%4,%5,%6,%7}, {%8,%9}, {%0,%1,%2,%3};"
        : "+f"(d[0]), "+f"(d[1]), "+f"(d[2]), "+f"(d[3])
        : "r"(a[0]), "r"(a[1]), "r"(a[2]), "r"(a[3]), "r"(b0), "r"(b1));
}

// ---------------- prep: fuse edge weights, fp16 B-fragment pack + bias ----------------
__global__ void kan_prep(const float* __restrict__ coeff, const float* __restrict__ bw,
                         const float* __restrict__ bb, const float* __restrict__ ew) {
    int i = blockIdx.x;
    if (i < IN_F) {                     // weight pack: 288 = 9 f x 32 j
        int t = threadIdx.x;
        int f = t >> 5, j = t & 31;
        float e = ew[i * OUT_F + j];
        float v = e * ((f == 0) ? bw[i * OUT_F + j] : coeff[(i * OUT_F + j) * 8 + (f - 1)]);

        int ci = i >> 4, ch = i & 15;
        int ks = ci * KSC + f;          // k16-step
        int kw = ch >> 1, half = ch & 1;
        int lane = (j & 7) * 4 + (kw & 3);
        int nt = j >> 3, h = nt >> 1;
        int slot = (nt & 1) * 2 + (kw >> 2);
        int idx = (((ks * 2 + h) * 32 + lane) * 4 + slot) * 2 + half;
        ((__half*)g_wf)[idx] = __float2half_rn(v);
    } else if (threadIdx.x < OUT_F) {   // bias block
        int j = threadIdx.x;
        float s = 0.0f;
        #pragma unroll 4
        for (int ii = 0; ii < IN_F; ii++) s += ew[ii * OUT_F + j] * bb[ii * OUT_F + j];
        g_bias[j] = s;
    }
}

// ---------------- main ----------------
__global__ void __launch_bounds__(THREADS, 2) kan_main(const float* __restrict__ x,
                                                       float* __restrict__ out) {
    extern __shared__ __align__(16) char sm[];
    const uint32_t smb = smem_u32(sm);
    const int tid = threadIdx.x;
    const int w = tid >> 5;              // MMA warp: rows w*16..w*16+15
    const int L = tid & 31;
    const int ch2 = tid & 7;             // producer channel-pair (chs 2*ch2, 2*ch2+1)
    const int rg = tid >> 3;             // producer row slot (0..31), rows rg+32p
    const size_t tile = (size_t)blockIdx.x * TILE_M;

    float q[7];
    const float D2 = DELTA * DELTA;
    #pragma unroll
    for (int k = 0; k < 7; k++) q[k] = __expf(-D2 * ((float)k + 0.5f));

    float acc[16];
    #pragma unroll
    for (int i = 0; i < 16; i++) acc[i] = 0.0f;

    // producer store bases: row r = rg+32p -> block b=r>>4, row-in-16 rr=r&15
    uint32_t off[4];
    #pragma unroll
    for (int p = 0; p < 4; p++) {
        int r = rg + 32 * p, b = r >> 4, rr = r & 15;
        off[p] = (uint32_t)(b * WBLK + ((rr & 7) * 4 + (ch2 & 3)) * 16
                            + ((rr >> 3) + 2 * (ch2 >> 2)) * 4);
    }

    const float2* xb = (const float2*)x;
    const size_t xbase = (tile + rg) * (IN_F / 2) + ch2;   // float2 index; +p*32*64, +c*8

    // consumer A-fragment base (buffer 0)
    const uint32_t lmb = smb + (uint32_t)(w * WBLK + L * 16);

    // ---- produce one (p) row-pair into buffer nb from xc ----
    #define PRODUCE_P(p, nb, xc) do {                                             \
        float2 X = (xc)[p];                                                       \
        float fa0[9], fa1[9];                                                     \
        fa0[0] = X.x * (0.5f * tanh_approx(0.5f * X.x) + 0.5f);                   \
        fa1[0] = X.y * (0.5f * tanh_approx(0.5f * X.y) + 0.5f);                   \
        {                                                                         \
            float wz0 = (X.x - C0_CONST) * INV_S;                                 \
            float wz1 = (X.y - C0_CONST) * INV_S;                                 \
            float t0 = __expf(DELTA * wz0), t1 = __expf(DELTA * wz1);             \
            float b0 = __expf(-0.5f * wz0 * wz0), b1 = __expf(-0.5f * wz1 * wz1); \
            fa0[1] = b0; fa1[1] = b1;                                             \
            _Pragma("unroll")                                                     \
            for (int kk = 0; kk < 7; kk++) {                                      \
                b0 *= t0 * q[kk]; b1 *= t1 * q[kk];                               \
                fa0[2 + kk] = b0; fa1[2 + kk] = b1;                               \
            }                                                                     \
        }                                                                         \
        char* abuf = sm + (nb) * ABUF;                                            \
        _Pragma("unroll")                                                         \
        for (int f = 0; f < 9; f++)                                               \
            *(uint32_t*)(abuf + off[p] + f * 512) = fh2(fa1[f], fa0[f]);          \
    } while (0)

    #define MMA_STEP(c, ks, buf) do {                                             \
        const uint4* __restrict__ wq = g_wf + (size_t)(((c) * KSC + (ks)) * 2) * 32 + L; \
        uint4 b0 = wq[0];                                                         \
        uint4 b1 = wq[32];                                                        \
        uint32_t a[4];                                                            \
        asm volatile("ld.shared.v4.b32 {%0,%1,%2,%3}, [%4];"                      \
                     : "=r"(a[0]), "=r"(a[1]), "=r"(a[2]), "=r"(a[3])             \
                     : "r"(lmb + (buf) * ABUF + (ks) * 512));                     \
        mma16816h(acc + 0,  a, b0.x, b0.y);                                       \
        mma16816h(acc + 4,  a, b0.z, b0.w);                                       \
        mma16816h(acc + 8,  a, b1.x, b1.y);                                       \
        mma16816h(acc + 12, a, b1.z, b1.w);                                       \
    } while (0)

    // ---- preloop: produce chunk 0 into buf 0; prefetch x(chunk 1) ----
    float2 xA[4];
    {
        float2 xc[4];
        #pragma unroll
        for (int p = 0; p < 4; p++) xc[p] = xb[xbase + (size_t)p * 32 * (IN_F / 2)];
        PRODUCE_P(0, 0, xc);
        PRODUCE_P(1, 0, xc);
        PRODUCE_P(2, 0, xc);
        PRODUCE_P(3, 0, xc);
    }
    #pragma unroll
    for (int p = 0; p < 4; p++) xA[p] = xb[xbase + (size_t)p * 32 * (IN_F / 2) + 8];
    __syncthreads();

    // ---- main pipeline: MMA(c) with produce(c+1) interleaved ----
    #pragma unroll 1
    for (int c = 0; c < NCHUNKS - 1; c++) {
        const int buf = c & 1;
        float2 xc[4];
        #pragma unroll
        for (int p = 0; p < 4; p++) xc[p] = xA[p];
        const int cn = (c + 2 < NCHUNKS) ? (c + 2) : (NCHUNKS - 1);  // clamp (dup load, unused)
        #pragma unroll
        for (int p = 0; p < 4; p++)
            xA[p] = xb[xbase + (size_t)p * 32 * (IN_F / 2) + (size_t)cn * 8];

        MMA_STEP(c, 0, buf);
        PRODUCE_P(0, buf ^ 1, xc);
        MMA_STEP(c, 1, buf);
        PRODUCE_P(1, buf ^ 1, xc);
        MMA_STEP(c, 2, buf);
        PRODUCE_P(2, buf ^ 1, xc);
        MMA_STEP(c, 3, buf);
        PRODUCE_P(3, buf ^ 1, xc);
        MMA_STEP(c, 4, buf);
        MMA_STEP(c, 5, buf);
        MMA_STEP(c, 6, buf);
        MMA_STEP(c, 7, buf);
        MMA_STEP(c, 8, buf);
        __syncthreads();
    }
    // final chunk: MMA only
    {
        const int buf = (NCHUNKS - 1) & 1;
        #pragma unroll
        for (int ks = 0; ks < KSC; ks++) MMA_STEP(NCHUNKS - 1, ks, buf);
    }

    // ---- epilogue: fragment -> global, + bias ----
    size_t r0 = tile + w * 16 + (L >> 2);
    int cb = (L & 3) * 2;
    #pragma unroll
    for (int nt = 0; nt < 4; nt++) {
        int col = nt * 8 + cb;
        float b0 = g_bias[col], b1 = g_bias[col + 1];
        float2 v0 = make_float2(acc[nt * 4 + 0] + b0, acc[nt * 4 + 1] + b1);
        float2 v1 = make_float2(acc[nt * 4 + 2] + b0, acc[nt * 4 + 3] + b1);
        *(float2*)(out + r0 * OUT_F + col)       = v0;
        *(float2*)(out + (r0 + 8) * OUT_F + col) = v1;
    }
}

// ---------------- launch ----------------
extern "C" void kernel_launch(void* const* d_in, const int* in_sizes, int n_in,
                              void* d_out, int out_size) {
    const float* x     = (const float*)d_in[0];
    const float* coeff = (const float*)d_in[1];
    const float* bw    = (const float*)d_in[2];
    const float* bb    = (const float*)d_in[3];
    const float* ew    = (const float*)d_in[4];
    float* out         = (float*)d_out;

    int n_rows = in_sizes[0] / IN_F;           // 131072
    int grid   = n_rows / TILE_M;              // 1024

    cudaFuncSetAttribute(kan_main, cudaFuncAttributeMaxDynamicSharedMemorySize, SMEM_TOTAL);

    kan_prep<<<IN_F + 1, 288>>>(coeff, bw, bb, ew);
    kan_main<<<grid, THREADS, SMEM_TOTAL>>>(x, out);
}

// round 16
// speedup vs baseline: 6.7738x; 1.3705x over previous
#include <cuda_runtime.h>
#include <cuda_fp16.h>
#include <cstdint>

// KAN layer as single-slab fp16 warp-MMA GEMM with REGISTER-RESIDENT A.
//   out[131072,32] = F[131072,1152] x W[1152,32] + bias
//   k = f*16 + ch  ->  one k16-step == one feature across 16 channels.
//   m16n8k16 A-fragment of lane L = rows {L>>2, +8} x chs {cb,cb+1,cb+8,cb+9}
//   (cb = 2*(L&3)), so each lane computes features for exactly its own 8
//   elements: A never touches SMEM. No STS/LDS, no barriers, no smem at all.

#define IN_F    128
#define OUT_F   32
#define TILE_M  128
#define THREADS 256
#define NCHUNKS 8
#define KSC     9                        // k16-steps per chunk (one per feature)
#define NKS     (NCHUNKS * KSC)          // 72

#define C0_CONST (-0.45454545454545453f)
#define SPACING  (0.400001f)
#define INV_S    (1.0f / SPACING)
#define DELTA    (0.18181818181818182f / SPACING)

// W in B-fragment order: uint4[(ks*2 + h)*32 + lane] = {nt=2h:{b0,b1}, nt=2h+1:{b0,b1}}
__device__ uint4 g_wf[NKS * 2 * 32];
__device__ float g_bias[OUT_F];

// ---------------- helpers ----------------
static __device__ __forceinline__ uint32_t fh2(float hi, float lo) {
    uint32_t r;
    asm("cvt.rn.f16x2.f32 %0, %1, %2;" : "=r"(r) : "f"(hi), "f"(lo));
    return r;
}
static __device__ __forceinline__ float tanh_approx(float v) {
    float r;
    asm("tanh.approx.f32 %0, %1;" : "=f"(r) : "f"(v));
    return r;
}
static __device__ __forceinline__ void mma16816h(float* d, const uint32_t* a,
                                                 uint32_t b0, uint32_t b1) {
    asm volatile(
        "mma.sync.aligned.m16n8k16.row.col.f32.f16.f16.f32 "
        "{%0,%1,%2,%3}, {%4,%5,%6,%7}, {%8,%9}, {%0,%1,%2,%3};"
        : "+f"(d[0]), "+f"(d[1]), "+f"(d[2]), "+f"(d[3])
        : "r"(a[0]), "r"(a[1]), "r"(a[2]), "r"(a[3]), "r"(b0), "r"(b1));
}

// ---------------- prep: fuse edge weights, fp16 B-fragment pack + bias ----------------
__global__ void kan_prep(const float* __restrict__ coeff, const float* __restrict__ bw,
                         const float* __restrict__ bb, const float* __restrict__ ew) {
    int i = blockIdx.x;
    if (i < IN_F) {                     // weight pack: 288 = 9 f x 32 j
        int t = threadIdx.x;
        int f = t >> 5, j = t & 31;
        float e = ew[i * OUT_F + j];
        float v = e * ((f == 0) ? bw[i * OUT_F + j] : coeff[(i * OUT_F + j) * 8 + (f - 1)]);

        int ci = i >> 4, ch = i & 15;
        int ks = ci * KSC + f;          // k16-step
        int kw = ch >> 1, half = ch & 1;
        int lane = (j & 7) * 4 + (kw & 3);
        int nt = j >> 3, h = nt >> 1;
        int slot = (nt & 1) * 2 + (kw >> 2);
        int idx = (((ks * 2 + h) * 32 + lane) * 4 + slot) * 2 + half;
        ((__half*)g_wf)[idx] = __float2half_rn(v);
    } else if (threadIdx.x < OUT_F) {   // bias block
        int j = threadIdx.x;
        float s = 0.0f;
        #pragma unroll 4
        for (int ii = 0; ii < IN_F; ii++) s += ew[ii * OUT_F + j] * bb[ii * OUT_F + j];
        g_bias[j] = s;
    }
}

// ---------------- main: no shared memory, no barriers ----------------
__global__ void __launch_bounds__(THREADS) kan_main(const float* __restrict__ x,
                                                    float* __restrict__ out) {
    const int tid = threadIdx.x;
    const int w = tid >> 5;              // warp: rows w*16..w*16+15
    const int L = tid & 31;
    const int r0 = L >> 2;               // row-in-16 (this lane: rows r0, r0+8)
    const int cb = (L & 3) * 2;          // channel base (chs cb,cb+1,cb+8,cb+9)
    const size_t tile = (size_t)blockIdx.x * TILE_M;

    const float* xr0 = x + (tile + w * 16 + r0) * IN_F;
    const float* xr1 = xr0 + 8 * IN_F;

    float q[7];
    const float D2 = DELTA * DELTA;
    #pragma unroll
    for (int k = 0; k < 7; k++) q[k] = __expf(-D2 * ((float)k + 0.5f));

    float acc[16];
    #pragma unroll
    for (int i = 0; i < 16; i++) acc[i] = 0.0f;

    // prefetch chunk 0 (4 x LDG.64, 32B-sector coalesced within 4-lane groups)
    float2 p0 = *(const float2*)(xr0 + cb);
    float2 p1 = *(const float2*)(xr0 + cb + 8);
    float2 p2 = *(const float2*)(xr1 + cb);
    float2 p3 = *(const float2*)(xr1 + cb + 8);

    // one k16-step: pack this lane's 4 A-frag words from feature array f[8],
    // load B frags, 4 HMMA.  X order: [0..3]=row r0 chs {cb,cb+1,cb+8,cb+9},
    // [4..7]=row r0+8 same chs.  a0:(r0, k 2c..) a1:(r0+8) a2:(r0, k+8) a3:(r0+8, k+8)
    #define DO_KS(f) do {                                                    \
        uint32_t a[4];                                                       \
        a[0] = fh2((f)[1], (f)[0]);                                          \
        a[1] = fh2((f)[5], (f)[4]);                                          \
        a[2] = fh2((f)[3], (f)[2]);                                          \
        a[3] = fh2((f)[7], (f)[6]);                                          \
        uint4 B0 = wq[0], B1 = wq[32];                                       \
        wq += 64;                                                            \
        mma16816h(acc + 0,  a, B0.x, B0.y);                                  \
        mma16816h(acc + 4,  a, B0.z, B0.w);                                  \
        mma16816h(acc + 8,  a, B1.x, B1.y);                                  \
        mma16816h(acc + 12, a, B1.z, B1.w);                                  \
    } while (0)

    const uint4* __restrict__ wq = g_wf + L;

    #pragma unroll 1
    for (int c = 0; c < NCHUNKS; c++) {
        float X[8] = {p0.x, p0.y, p1.x, p1.y, p2.x, p2.y, p3.x, p3.y};
        if (c < NCHUNKS - 1) {           // prefetch next chunk
            int o = (c + 1) * 16;
            p0 = *(const float2*)(xr0 + o + cb);
            p1 = *(const float2*)(xr0 + o + cb + 8);
            p2 = *(const float2*)(xr1 + o + cb);
            p3 = *(const float2*)(xr1 + o + cb + 8);
        }

        // per-element transcendentals: silu + gaussian ladder seeds
        float sl[8], t[8], b[8];
        #pragma unroll
        for (int j = 0; j < 8; j++) {
            float Xj = X[j];
            sl[j] = Xj * (0.5f * tanh_approx(0.5f * Xj) + 0.5f);
            float wz = (Xj - C0_CONST) * INV_S;
            t[j] = __expf(DELTA * wz);
            b[j] = __expf(-0.5f * wz * wz);
        }

        DO_KS(sl);                        // f = 0 : silu
        DO_KS(b);                         // f = 1 : basis_0
        #pragma unroll
        for (int kk = 0; kk < 7; kk++) {  // f = 2..8 : ladder
            #pragma unroll
            for (int j = 0; j < 8; j++) b[j] *= t[j] * q[kk];
            DO_KS(b);
        }
    }

    // ---- epilogue: fragment -> global, + bias (L1-hit LDG) ----
    size_t ro = tile + w * 16 + (L >> 2);
    int cbo = (L & 3) * 2;
    #pragma unroll
    for (int nt = 0; nt < 4; nt++) {
        int col = nt * 8 + cbo;
        float b0 = g_bias[col], b1 = g_bias[col + 1];
        float2 v0 = make_float2(acc[nt * 4 + 0] + b0, acc[nt * 4 + 1] + b1);
        float2 v1 = make_float2(acc[nt * 4 + 2] + b0, acc[nt * 4 + 3] + b1);
        *(float2*)(out + ro * OUT_F + col)       = v0;
        *(float2*)(out + (ro + 8) * OUT_F + col) = v1;
    }
}

// ---------------- launch ----------------
extern "C" void kernel_launch(void* const* d_in, const int* in_sizes, int n_in,
                              void* d_out, int out_size) {
    const float* x     = (const float*)d_in[0];
    const float* coeff = (const float*)d_in[1];
    const float* bw    = (const float*)d_in[2];
    const float* bb    = (const float*)d_in[3];
    const float* ew    = (const float*)d_in[4];
    float* out         = (float*)d_out;

    int n_rows = in_sizes[0] / IN_F;           // 131072
    int grid   = n_rows / TILE_M;              // 1024

    kan_prep<<<IN_F + 1, 288>>>(coeff, bw, bb, ew);
    kan_main<<<grid, THREADS>>>(x, out);
}